// round 15
// baseline (speedup 1.0000x reference)
#include <cuda_runtime.h>
#include <cuda_fp16.h>
#include <cstdint>

#define NN      50000
#define EE      800000
#define ETOT    (EE + NN)        // edges + self loops (850000, even)
#define IN_CH   256
#define HIDC    64
#define HEADS   2
#define C1      (HEADS * HIDC)   // 128
#define BN_EPS  1e-5f

// ---------------- scratch (static device arrays; no allocation) --------------
__device__ __half g_xl1h[NN * C1];   // fp16 edge operands
__device__ __half g_xr1h[NN * C1];
__device__ float  g_sum1[NN * HEADS];
__device__ float  g_h1 [NN * C1];    // layer-1: accumulates sum(p * xl), fp32
__device__ __half g_xl2h[NN * HIDC];
__device__ __half g_xr2h[NN * HIDC];
__device__ float  g_sum2[NN];
__device__ float  g_h2 [NN * HIDC];  // layer-2: accumulates sum(p * xl), fp32
__device__ __half g_w1t[2 * C1 * IN_CH];   // W1 cat, TRANSPOSED [2M][K] fp16
__device__ __half g_w2t[2 * HIDC * C1];    // W2 cat, TRANSPOSED [2M][K] fp16

// ---------------- helpers ----------------------------------------------------
__device__ __forceinline__ float lrelu(float v) { return v > 0.f ? v : 0.2f * v; }

__device__ __forceinline__ void red_add_v4(float* addr, float4 v) {
    asm volatile("red.global.add.v4.f32 [%0], {%1, %2, %3, %4};"
                 :: "l"(addr), "f"(v.x), "f"(v.y), "f"(v.z), "f"(v.w) : "memory");
}

__device__ __forceinline__ uint32_t smem_u32(const void* p) {
    return (uint32_t)__cvta_generic_to_shared(p);
}

#define LDSM_X4(r0, r1, r2, r3, addr) \
    asm volatile("ldmatrix.sync.aligned.m8n8.x4.shared.b16 {%0,%1,%2,%3}, [%4];" \
                 : "=r"(r0), "=r"(r1), "=r"(r2), "=r"(r3) : "r"(addr))

#define MMA16816(acc, a0, a1, a2, a3, b0, b1) \
    asm volatile("mma.sync.aligned.m16n8k16.row.col.f32.f16.f16.f32 " \
                 "{%0,%1,%2,%3}, {%4,%5,%6,%7}, {%8,%9}, {%0,%1,%2,%3};" \
                 : "+f"((acc)[0]), "+f"((acc)[1]), "+f"((acc)[2]), "+f"((acc)[3]) \
                 : "r"(a0), "r"(a1), "r"(a2), "r"(a3), "r"(b0), "r"(b1))

// logit contribution for 8 fp16 channel-pairs vs att coefficients
__device__ __forceinline__ float logit8(uint4 ar, uint4 br, float4 at0, float4 at1)
{
    const __half2* ah = (const __half2*)&ar;
    const __half2* bh = (const __half2*)&br;
    float2 a0 = __half22float2(ah[0]), a1 = __half22float2(ah[1]);
    float2 a2 = __half22float2(ah[2]), a3 = __half22float2(ah[3]);
    float2 b0 = __half22float2(bh[0]), b1 = __half22float2(bh[1]);
    float2 b2 = __half22float2(bh[2]), b3 = __half22float2(bh[3]);
    return at0.x * lrelu(a0.x + b0.x) + at0.y * lrelu(a0.y + b0.y)
         + at0.z * lrelu(a1.x + b1.x) + at0.w * lrelu(a1.y + b1.y)
         + at1.x * lrelu(a2.x + b2.x) + at1.y * lrelu(a2.y + b2.y)
         + at1.z * lrelu(a3.x + b3.x) + at1.w * lrelu(a3.y + b3.y);
}

__device__ __forceinline__ void scale8(uint4 ar, float p, float4& v0, float4& v1)
{
    const __half2* ah = (const __half2*)&ar;
    float2 a0 = __half22float2(ah[0]), a1 = __half22float2(ah[1]);
    float2 a2 = __half22float2(ah[2]), a3 = __half22float2(ah[3]);
    v0 = make_float4(a0.x * p, a0.y * p, a1.x * p, a1.y * p);
    v1 = make_float4(a2.x * p, a2.y * p, a3.x * p, a3.y * p);
}

// ---------------- weight convert (both layers, one launch) -------------------
// fp32 [K][M] x2 -> fp16 transposed [2M][K]
__global__ void k_wcvt(const float* __restrict__ W1l, const float* __restrict__ W1r,
                       const float* __restrict__ W2l, const float* __restrict__ W2r)
{
    constexpr int N1 = 2 * C1 * IN_CH;          // 65536
    constexpr int N2 = 2 * HIDC * C1;           // 16384
    int tid = blockIdx.x * blockDim.x + threadIdx.x;
    if (tid < N1) {
        int c = tid / IN_CH, k = tid % IN_CH;
        float v = (c < C1) ? W1l[k * C1 + c] : W1r[k * C1 + (c - C1)];
        g_w1t[tid] = __float2half(v);
    } else if (tid < N1 + N2) {
        int t2 = tid - N1;
        int c = t2 / C1, k = t2 % C1;
        float v = (c < HIDC) ? W2l[k * HIDC + c] : W2r[k * HIDC + (c - HIDC)];
        g_w2t[t2] = __float2half(v);
    }
}

// ---------------- tensor-core dual GEMM --------------------------------------
// LAYER 1: A = x (fp32 arg), K=256, MHALF=128, out = g_x{l,r}1h
// LAYER 2: A = BN/ELU(g_h1 / g_sum1) computed in staging (fused layer-1
//          epilogue), K=128, MHALF=64, out = g_x{l,r}2h. Restores g_h1 and
//          g_sum1 to zero (g_sum1 AFTER the barrier — staging reads it).
// Block: 512 threads = 16 warps (8 row-groups x 2 col-warps), 128-row tile.
template<int LAYER>
__global__ __launch_bounds__(512) void k_mma_gemm(
    const float* __restrict__ Aparam,
    const float* __restrict__ bl, const float* __restrict__ br,
    const float* __restrict__ bias,
    const float* __restrict__ bg, const float* __restrict__ bb,
    const float* __restrict__ bm, const float* __restrict__ bv)
{
    constexpr int K     = (LAYER == 1) ? IN_CH : C1;
    constexpr int MHALF = (LAYER == 1) ? C1 : HIDC;
    constexpr int M2    = 2 * MHALF;
    constexpr int ROWS  = 128;
    constexpr int SK    = K + 8;          // padded stride (halves)
    constexpr int NT    = MHALF / 8;      // mma n-tiles per warp

    const __half* Wt   = (LAYER == 1) ? g_w1t : g_w2t;
    __half*       outl = (LAYER == 1) ? g_xl1h : g_xl2h;
    __half*       outr = (LAYER == 1) ? g_xr1h : g_xr2h;

    extern __shared__ __half sh[];
    __half* As = sh;                      // [ROWS][SK]
    __half* Ws = sh + ROWS * SK;          // [M2][SK]

    const int tid = threadIdx.x;
    const int r0  = blockIdx.x * ROWS;

    // stage A (fp32 -> fp16), zero-pad OOB rows
    for (int i = tid * 4; i < ROWS * K; i += 512 * 4) {
        int row = i / K, kk = i % K;
        int node = r0 + row;
        float4 v = make_float4(0.f, 0.f, 0.f, 0.f);
        if (node < NN) {
            if (LAYER == 1) {
                v = *(const float4*)&Aparam[(size_t)node * K + kk];
            } else {
                // fused layer-1 epilogue: /sum + bias + bn + elu
                float4 hv = *(const float4*)&g_h1[(size_t)node * K + kk];
                float inv_s = __fdividef(1.f, g_sum1[node * 2 + (kk >> 6)]);
                float4 bi = *(const float4*)&bias[kk];
                float4 gm = *(const float4*)&bg[kk];
                float4 bt = *(const float4*)&bb[kk];
                float4 mu = *(const float4*)&bm[kk];
                float4 vr = *(const float4*)&bv[kk];
                float x0 = (hv.x * inv_s + bi.x - mu.x) * rsqrtf(vr.x + BN_EPS) * gm.x + bt.x;
                float x1 = (hv.y * inv_s + bi.y - mu.y) * rsqrtf(vr.y + BN_EPS) * gm.y + bt.y;
                float x2 = (hv.z * inv_s + bi.z - mu.z) * rsqrtf(vr.z + BN_EPS) * gm.z + bt.z;
                float x3 = (hv.w * inv_s + bi.w - mu.w) * rsqrtf(vr.w + BN_EPS) * gm.w + bt.w;
                v.x = x0 > 0.f ? x0 : expm1f(x0);
                v.y = x1 > 0.f ? x1 : expm1f(x1);
                v.z = x2 > 0.f ? x2 : expm1f(x2);
                v.w = x3 > 0.f ? x3 : expm1f(x3);
                *(float4*)&g_h1[(size_t)node * K + kk] = make_float4(0.f, 0.f, 0.f, 0.f);
            }
        }
        __half2* dst = (__half2*)&As[row * SK + kk];
        dst[0] = __floats2half2_rn(v.x, v.y);
        dst[1] = __floats2half2_rn(v.z, v.w);
    }
    // stage Wt (fp16, already transposed)
    for (int i = tid * 8; i < M2 * K; i += 512 * 8) {
        int row = i / K, kk = i % K;
        *(uint4*)&Ws[row * SK + kk] = *(const uint4*)&Wt[row * K + kk];
    }
    __syncthreads();   // ALL staging reads (incl. g_sum1) complete here

    // layer 2: restore g_sum1 zero state AFTER the barrier (rows exclusive
    // to this block; not read again in this kernel)
    if (LAYER == 2 && tid < 2 * ROWS) {
        int idx = blockIdx.x * (2 * ROWS) + tid;
        if (idx < 2 * NN) g_sum1[idx] = 0.f;
    }

    const int warp = tid >> 5, lane = tid & 31;
    const int wr = warp >> 1, wc = warp & 1;
    const int lr = lane & 7,  g  = lane >> 3;

    const uint32_t aAddr0 = smem_u32(As) +
        (uint32_t)(((wr * 16 + lr + (g & 1) * 8) * SK + (g >> 1) * 8) * 2);
    const int rowB_off = lr + (g >> 1) * 8;
    const int colB     = (g & 1) * 8;
    const uint32_t wsBase = smem_u32(Ws);

    float acc[NT][4];
#pragma unroll
    for (int nt = 0; nt < NT; nt++)
#pragma unroll
        for (int j = 0; j < 4; j++) acc[nt][j] = 0.f;

    for (int kc = 0; kc < K / 16; kc++) {
        const int k0 = kc * 16;
        uint32_t a0, a1, a2, a3;
        LDSM_X4(a0, a1, a2, a3, aAddr0 + (uint32_t)(k0 * 2));
#pragma unroll
        for (int ntp = 0; ntp < NT / 2; ntp++) {
            int n0p = wc * MHALF + ntp * 16;
            uint32_t b0, b1, b2, b3;
            LDSM_X4(b0, b1, b2, b3,
                    wsBase + (uint32_t)(((n0p + rowB_off) * SK + k0 + colB) * 2));
            MMA16816(acc[2 * ntp],     a0, a1, a2, a3, b0, b1);
            MMA16816(acc[2 * ntp + 1], a0, a1, a2, a3, b2, b3);
        }
    }

    // epilogue: +bias, fp16 store
    const float* bs  = wc ? br : bl;
    __half*      out = wc ? outr : outl;
    const int row0 = r0 + wr * 16 + (lane >> 2);
    const int row1 = row0 + 8;
    const int cb   = (lane & 3) * 2;
#pragma unroll
    for (int nt = 0; nt < NT; nt++) {
        int lc = nt * 8 + cb;
        float b0v = bs[lc], b1v = bs[lc + 1];
        if (row0 < NN)
            *(__half2*)&out[(size_t)row0 * MHALF + lc] =
                __floats2half2_rn(acc[nt][0] + b0v, acc[nt][1] + b1v);
        if (row1 < NN)
            *(__half2*)&out[(size_t)row1 * MHALF + lc] =
                __floats2half2_rn(acc[nt][2] + b0v, acc[nt][3] + b1v);
    }
}

// ---------------- layer-1 FUSED edge pass: 2 edges per thread ----------------
__global__ void k_edge1(const int* __restrict__ ei, const float* __restrict__ att)
{
    int gid = blockIdx.x * blockDim.x + threadIdx.x;
    int gp  = gid >> 4;                    // 16 lanes per edge PAIR
    int l   = gid & 15;
    int e0  = gp * 2;
    if (e0 >= ETOT) return;

    int src0, dst0, src1, dst1;
    if (e0 < EE) {
        int2 sp = *(const int2*)&ei[e0];
        int2 dp = *(const int2*)&ei[EE + e0];
        src0 = sp.x; src1 = sp.y; dst0 = dp.x; dst1 = dp.y;
    } else {
        src0 = dst0 = e0 - EE;
        src1 = dst1 = e0 + 1 - EE;
    }

    int ch = l * 8;
    uint4 ar0 = *(const uint4*)&g_xl1h[(size_t)src0 * C1 + ch];
    uint4 br0 = *(const uint4*)&g_xr1h[(size_t)dst0 * C1 + ch];
    uint4 ar1 = *(const uint4*)&g_xl1h[(size_t)src1 * C1 + ch];
    uint4 br1 = *(const uint4*)&g_xr1h[(size_t)dst1 * C1 + ch];

    float4 at0 = *(const float4*)&att[ch];
    float4 at1 = *(const float4*)&att[ch + 4];

    float s0 = logit8(ar0, br0, at0, at1);
    float s1 = logit8(ar1, br1, at0, at1);

    s0 += __shfl_xor_sync(0xffffffffu, s0, 4);
    s1 += __shfl_xor_sync(0xffffffffu, s1, 4);
    s0 += __shfl_xor_sync(0xffffffffu, s0, 2);
    s1 += __shfl_xor_sync(0xffffffffu, s1, 2);
    s0 += __shfl_xor_sync(0xffffffffu, s0, 1);
    s1 += __shfl_xor_sync(0xffffffffu, s1, 1);

    float p0 = __expf(s0);
    float p1 = __expf(s1);

    if ((l & 7) == 0) {
        int h = l >> 3;
        atomicAdd(&g_sum1[(size_t)dst0 * 2 + h], p0);
        atomicAdd(&g_sum1[(size_t)dst1 * 2 + h], p1);
    }

    float4 v0, v1;
    scale8(ar0, p0, v0, v1);
    float* hb0 = &g_h1[(size_t)dst0 * C1 + ch];
    red_add_v4(hb0,     v0);
    red_add_v4(hb0 + 4, v1);

    scale8(ar1, p1, v0, v1);
    float* hb1 = &g_h1[(size_t)dst1 * C1 + ch];
    red_add_v4(hb1,     v0);
    red_add_v4(hb1 + 4, v1);
}

// ---------------- layer-2 FUSED edge pass: 2 edges per thread ----------------
__global__ void k_edge2(const int* __restrict__ ei, const float* __restrict__ att)
{
    int gid = blockIdx.x * blockDim.x + threadIdx.x;
    int gp  = gid >> 3;                    // 8 lanes per edge PAIR
    int l   = gid & 7;
    int e0  = gp * 2;
    if (e0 >= ETOT) return;

    int src0, dst0, src1, dst1;
    if (e0 < EE) {
        int2 sp = *(const int2*)&ei[e0];
        int2 dp = *(const int2*)&ei[EE + e0];
        src0 = sp.x; src1 = sp.y; dst0 = dp.x; dst1 = dp.y;
    } else {
        src0 = dst0 = e0 - EE;
        src1 = dst1 = e0 + 1 - EE;
    }

    int ch = l * 8;
    uint4 ar0 = *(const uint4*)&g_xl2h[(size_t)src0 * HIDC + ch];
    uint4 br0 = *(const uint4*)&g_xr2h[(size_t)dst0 * HIDC + ch];
    uint4 ar1 = *(const uint4*)&g_xl2h[(size_t)src1 * HIDC + ch];
    uint4 br1 = *(const uint4*)&g_xr2h[(size_t)dst1 * HIDC + ch];

    float4 at0 = *(const float4*)&att[ch];
    float4 at1 = *(const float4*)&att[ch + 4];

    float s0 = logit8(ar0, br0, at0, at1);
    float s1 = logit8(ar1, br1, at0, at1);

    s0 += __shfl_xor_sync(0xffffffffu, s0, 4);
    s1 += __shfl_xor_sync(0xffffffffu, s1, 4);
    s0 += __shfl_xor_sync(0xffffffffu, s0, 2);
    s1 += __shfl_xor_sync(0xffffffffu, s1, 2);
    s0 += __shfl_xor_sync(0xffffffffu, s0, 1);
    s1 += __shfl_xor_sync(0xffffffffu, s1, 1);

    float p0 = __expf(s0);
    float p1 = __expf(s1);

    if (l == 0) {
        atomicAdd(&g_sum2[dst0], p0);
        atomicAdd(&g_sum2[dst1], p1);
    }

    float4 v0, v1;
    scale8(ar0, p0, v0, v1);
    float* hb0 = &g_h2[(size_t)dst0 * HIDC + ch];
    red_add_v4(hb0,     v0);
    red_add_v4(hb0 + 4, v1);

    scale8(ar1, p1, v0, v1);
    float* hb1 = &g_h2[(size_t)dst1 * HIDC + ch];
    red_add_v4(hb1,     v0);
    red_add_v4(hb1 + 4, v1);
}

// ---------------- final: /sum, +bias2, bn2, elu, classifier, sigmoid ---------
__global__ void k_final(const float* __restrict__ bias,
                        const float* __restrict__ bg, const float* __restrict__ bb,
                        const float* __restrict__ bm, const float* __restrict__ bv,
                        const float* __restrict__ Wc, const float* __restrict__ bc,
                        float* __restrict__ out)
{
    int warp = (blockIdx.x * blockDim.x + threadIdx.x) >> 5;
    int lane = threadIdx.x & 31;
    if (warp >= NN) return;

    float inv_s = __fdividef(1.f, g_sum2[warp]);
    int c = lane * 2;
    float2 h  = *(const float2*)&g_h2[(size_t)warp * HIDC + c];
    float x0 = h.x * inv_s + bias[c + 0];
    float x1 = h.y * inv_s + bias[c + 1];
    x0 = (x0 - bm[c + 0]) * rsqrtf(bv[c + 0] + BN_EPS) * bg[c + 0] + bb[c + 0];
    x1 = (x1 - bm[c + 1]) * rsqrtf(bv[c + 1] + BN_EPS) * bg[c + 1] + bb[c + 1];
    x0 = x0 > 0.f ? x0 : expm1f(x0);
    x1 = x1 > 0.f ? x1 : expm1f(x1);

    *(float2*)&g_h2[(size_t)warp * HIDC + c] = make_float2(0.f, 0.f);
    if (lane == 0) g_sum2[warp] = 0.f;

    float z = x0 * Wc[c + 0] + x1 * Wc[c + 1];
    z += __shfl_xor_sync(0xffffffffu, z, 16);
    z += __shfl_xor_sync(0xffffffffu, z, 8);
    z += __shfl_xor_sync(0xffffffffu, z, 4);
    z += __shfl_xor_sync(0xffffffffu, z, 2);
    z += __shfl_xor_sync(0xffffffffu, z, 1);

    if (lane == 0) {
        z += bc[0];
        out[warp] = 1.f / (1.f + __expf(-z));
    }
}

// ---------------- launch -----------------------------------------------------
extern "C" void kernel_launch(void* const* d_in, const int* in_sizes, int n_in,
                              void* d_out, int out_size)
{
    const float* x    = (const float*)d_in[0];
    const int*   ei   = (const int*)  d_in[1];
    const float* W1l  = (const float*)d_in[2];
    const float* b1l  = (const float*)d_in[3];
    const float* W1r  = (const float*)d_in[4];
    const float* b1r  = (const float*)d_in[5];
    const float* att1 = (const float*)d_in[6];
    const float* bias1= (const float*)d_in[7];
    const float* bn1g = (const float*)d_in[8];
    const float* bn1b = (const float*)d_in[9];
    const float* bn1m = (const float*)d_in[10];
    const float* bn1v = (const float*)d_in[11];
    const float* W2l  = (const float*)d_in[12];
    const float* b2l  = (const float*)d_in[13];
    const float* W2r  = (const float*)d_in[14];
    const float* b2r  = (const float*)d_in[15];
    const float* att2 = (const float*)d_in[16];
    const float* bias2= (const float*)d_in[17];
    const float* bn2g = (const float*)d_in[18];
    const float* bn2b = (const float*)d_in[19];
    const float* bn2m = (const float*)d_in[20];
    const float* bn2v = (const float*)d_in[21];
    const float* Wc   = (const float*)d_in[22];
    const float* bc   = (const float*)d_in[23];
    float* out = (float*)d_out;

    const int edge1Blocks = ((ETOT / 2) * 16 + 255) / 256;
    const int edge2Blocks = ((ETOT / 2) * 8  + 255) / 256;
    const int gemmBlocks  = (NN + 127) / 128;            // 391
    const int wcvtN       = 2 * C1 * IN_CH + 2 * HIDC * C1;

    const int smem1 = (128 * (IN_CH + 8) + 2 * C1   * (IN_CH + 8)) * 2;  // ~198 KB
    const int smem2 = (128 * (C1 + 8)    + 2 * HIDC * (C1 + 8))    * 2;  // ~68 KB
    static bool attr_set = false;
    if (!attr_set) {
        cudaFuncSetAttribute(k_mma_gemm<1>, cudaFuncAttributeMaxDynamicSharedMemorySize, smem1);
        cudaFuncSetAttribute(k_mma_gemm<2>, cudaFuncAttributeMaxDynamicSharedMemorySize, smem2);
        attr_set = true;
    }

    // weight conversion (both layers)
    k_wcvt<<<(wcvtN + 255) / 256, 256>>>(W1l, W1r, W2l, W2r);

    // layer 1
    k_mma_gemm<1><<<gemmBlocks, 512, smem1>>>(x, b1l, b1r,
                                              nullptr, nullptr, nullptr, nullptr, nullptr);
    k_edge1<<<edge1Blocks, 256>>>(ei, att1);

    // layer 2 (layer-1 epilogue fused into gemm2 staging)
    k_mma_gemm<2><<<gemmBlocks, 512, smem2>>>(nullptr, b2l, b2r,
                                              bias1, bn1g, bn1b, bn1m, bn1v);
    k_edge2<<<edge2Blocks, 256>>>(ei, att2);

    // epilogue + classifier
    k_final<<<(NN * 32 + 255) / 256, 256>>>(bias2, bn2g, bn2b, bn2m, bn2v, Wc, bc, out);
}